// round 2
// baseline (speedup 1.0000x reference)
#include <cuda_runtime.h>
#include <math.h>

// ---------------------------------------------------------------------------
// ModelSimple: conv4d(1->5,k7)+ReLU -> conv4d(5->10,k7)+ReLU -> Linear -> sigmoid
// R1: packed fp32x2 FFMA (FFMA2) to use the full 128 MAC/cyc/SM fp32 datapath.
// ---------------------------------------------------------------------------

#define NB 128

typedef unsigned long long ull;

__device__ float g_h1[NB * 5 * 20736];
__device__ float g_h2[NB * 10 * 1296];

__device__ __forceinline__ ull pk2(float lo, float hi) {
    ull r; asm("mov.b64 %0,{%1,%2};" : "=l"(r) : "f"(lo), "f"(hi)); return r;
}
__device__ __forceinline__ void fma2(ull& d, ull a, ull b) {
    asm("fma.rn.f32x2 %0,%1,%2,%0;" : "+l"(d) : "l"(a), "l"(b));
}
__device__ __forceinline__ void upk2(ull v, float& lo, float& hi) {
    asm("mov.b64 {%0,%1},%2;" : "=f"(lo), "=f"(hi) : "l"(v));
}

// ---------------------------------------------------------------------------
// conv1: one block per (b, oh). 288 threads: tid -> (ow, od, ot-half).
// Accumulator pairs over ot: acc2[oc][j] holds (ot0+j, ot0+j+3).
// Weights staged per-kh into SMEM as duplicated (w,w) 8B pairs, layout [tap][oc].
// ---------------------------------------------------------------------------
__global__ __launch_bounds__(288, 1)
void conv1_kernel(const float* __restrict__ x,
                  const float* __restrict__ w1,
                  const float* __restrict__ b1)
{
    extern __shared__ float sm1[];
    float* xs = sm1;                       // 40824 floats
    ull*   wd = (ull*)(sm1 + 40824);       // 1715 dup-pairs (per-kh slice)

    const int blk = blockIdx.x;
    const int b  = blk / 12;
    const int oh = blk % 12;

    const float* xb = x + (size_t)b * 104976 + (size_t)oh * 5832;
    for (int i = threadIdx.x; i < 40824; i += 288) xs[i] = xb[i];

    const int tid = threadIdx.x;
    const int ow  = tid / 24;          // 0..11
    const int rem = tid % 24;
    const int od  = rem >> 1;          // 0..11
    const int ot0 = (rem & 1) * 6;     // 0 or 6

    ull acc2[5][3];
#pragma unroll
    for (int c = 0; c < 5; c++)
#pragma unroll
        for (int j = 0; j < 3; j++) acc2[c][j] = 0ull;

#pragma unroll 1
    for (int kh = 0; kh < 7; kh++) {
        __syncthreads();   // xs ready (kh=0) / wd reads done (kh>0)
        for (int i = tid; i < 1715; i += 288) {
            const int tap = i / 5;
            const int oc  = i - tap * 5;
            const float v = w1[oc * 2401 + kh * 343 + tap];
            wd[i] = pk2(v, v);
        }
        __syncthreads();

#pragma unroll 1
        for (int kw = 0; kw < 7; kw++) {
#pragma unroll
            for (int kd = 0; kd < 7; kd++) {
                const float* xp = xs + (((kh * 18) + (ow + kw)) * 18 + (od + kd)) * 18 + ot0;
                float xr[12];
#pragma unroll
                for (int i = 0; i < 12; i++) xr[i] = xp[i];
                ull q[9];
#pragma unroll
                for (int i = 0; i < 9; i++) q[i] = pk2(xr[i], xr[i + 3]);

                const ull* wrow = wd + (size_t)((kw * 7 + kd) * 7) * 5;
#pragma unroll
                for (int kt = 0; kt < 7; kt++) {
#pragma unroll
                    for (int oc = 0; oc < 5; oc++) {
                        const ull w = wrow[kt * 5 + oc];
                        fma2(acc2[oc][0], w, q[kt]);
                        fma2(acc2[oc][1], w, q[kt + 1]);
                        fma2(acc2[oc][2], w, q[kt + 2]);
                    }
                }
            }
        }
    }

    // h1 layout: [b][oc][oh][ow][od][ot]
    const size_t obase = (size_t)b * 103680 + (size_t)oh * 1728
                       + (size_t)ow * 144 + (size_t)od * 12 + ot0;
#pragma unroll
    for (int oc = 0; oc < 5; oc++) {
        const float bias = b1[oc];
#pragma unroll
        for (int j = 0; j < 3; j++) {
            float vlo, vhi;
            upk2(acc2[oc][j], vlo, vhi);
            vlo += bias; vhi += bias;
            g_h1[obase + (size_t)oc * 20736 + j]     = vlo > 0.f ? vlo : 0.f;
            g_h1[obase + (size_t)oc * 20736 + j + 3] = vhi > 0.f ? vhi : 0.f;
        }
    }
}

// ---------------------------------------------------------------------------
// conv2: one block per batch. 432 threads: tid -> (oh, ow, od, ot-half of 3).
// Accumulator pairs over oc: acc2[j][t'] holds (oc=2j, oc=2j+1) at ot=ot0+t'.
// Weights staged per (ic, kh) transposed [tap][ocpair] as natural 8B pairs.
// ---------------------------------------------------------------------------
__global__ __launch_bounds__(432, 1)
void conv2_kernel(const float* __restrict__ w2,
                  const float* __restrict__ b2)
{
    extern __shared__ float sm2[];
    float* xs  = sm2;                      // 20736 floats
    ull*   wd2 = (ull*)(sm2 + 20736);      // 1715 pairs (per ic,kh slice)

    const int b   = blockIdx.x;
    const int tid = threadIdx.x;
    const int t2  = tid >> 1;              // 0..215
    const int oh  = t2 / 36;               // 0..5
    const int ow  = (t2 / 6) % 6;          // 0..5
    const int od  = t2 % 6;                // 0..5
    const int ot0 = (tid & 1) * 3;         // 0 or 3

    ull acc2[5][3];
#pragma unroll
    for (int j = 0; j < 5; j++)
#pragma unroll
        for (int t = 0; t < 3; t++) acc2[j][t] = 0ull;

#pragma unroll 1
    for (int ic = 0; ic < 5; ic++) {
        __syncthreads();   // previous iteration's xs reads done
        const float* hb = g_h1 + ((size_t)b * 5 + ic) * 20736;
        for (int i = tid; i < 20736; i += 432) xs[i] = hb[i];

#pragma unroll 1
        for (int kh = 0; kh < 7; kh++) {
            __syncthreads();   // xs staged (kh=0) / wd2 reads done (kh>0)
            for (int i = tid; i < 1715; i += 432) {
                const int tap = i / 5;
                const int j   = i - tap * 5;
                const float vlo = w2[((size_t)(2 * j)     * 5 + ic) * 2401 + kh * 343 + tap];
                const float vhi = w2[((size_t)(2 * j + 1) * 5 + ic) * 2401 + kh * 343 + tap];
                wd2[i] = pk2(vlo, vhi);
            }
            __syncthreads();

#pragma unroll 1
            for (int kw = 0; kw < 7; kw++) {
#pragma unroll
                for (int kd = 0; kd < 7; kd++) {
                    const float* xp = xs + (((oh + kh) * 12 + (ow + kw)) * 12 + (od + kd)) * 12 + ot0;
                    float xr[9];
#pragma unroll
                    for (int i = 0; i < 9; i++) xr[i] = xp[i];
                    ull q[9];
#pragma unroll
                    for (int i = 0; i < 9; i++) q[i] = pk2(xr[i], xr[i]);

                    const ull* wrow = wd2 + (size_t)((kw * 7 + kd) * 7) * 5;
#pragma unroll
                    for (int kt = 0; kt < 7; kt++) {
#pragma unroll
                        for (int j = 0; j < 5; j++) {
                            const ull w = wrow[kt * 5 + j];
                            fma2(acc2[j][0], w, q[kt]);
                            fma2(acc2[j][1], w, q[kt + 1]);
                            fma2(acc2[j][2], w, q[kt + 2]);
                        }
                    }
                }
            }
        }
    }

    // h2 layout: [b][oc][oh][ow][od][ot]
    const size_t obase = (size_t)b * 12960 + (size_t)oh * 216
                       + (size_t)ow * 36 + (size_t)od * 6 + ot0;
#pragma unroll
    for (int j = 0; j < 5; j++) {
        const float blo = b2[2 * j];
        const float bhi = b2[2 * j + 1];
#pragma unroll
        for (int t = 0; t < 3; t++) {
            float vlo, vhi;
            upk2(acc2[j][t], vlo, vhi);
            vlo += blo; vhi += bhi;
            g_h2[obase + (size_t)(2 * j)     * 1296 + t] = vlo > 0.f ? vlo : 0.f;
            g_h2[obase + (size_t)(2 * j + 1) * 1296 + t] = vhi > 0.f ? vhi : 0.f;
        }
    }
}

// ---------------------------------------------------------------------------
// linear + sigmoid: one block per batch row, dot over 12960 + reduce.
// ---------------------------------------------------------------------------
__global__ __launch_bounds__(256)
void linear_kernel(const float* __restrict__ wl,
                   const float* __restrict__ bl,
                   float* __restrict__ out)
{
    const int b = blockIdx.x;
    const float* h = g_h2 + (size_t)b * 12960;
    float s = 0.f;
    for (int i = threadIdx.x; i < 12960; i += 256)
        s = fmaf(h[i], wl[i], s);

    __shared__ float red[8];
#pragma unroll
    for (int o = 16; o; o >>= 1) s += __shfl_xor_sync(0xFFFFFFFFu, s, o);
    if ((threadIdx.x & 31) == 0) red[threadIdx.x >> 5] = s;
    __syncthreads();
    if (threadIdx.x < 32) {
        s = (threadIdx.x < 8) ? red[threadIdx.x] : 0.f;
#pragma unroll
        for (int o = 4; o; o >>= 1) s += __shfl_xor_sync(0xFFFFFFFFu, s, o);
        if (threadIdx.x == 0) {
            const float z = s + bl[0];
            out[b] = 1.f / (1.f + expf(-z));
        }
    }
}

// ---------------------------------------------------------------------------
extern "C" void kernel_launch(void* const* d_in, const int* in_sizes, int n_in,
                              void* d_out, int out_size)
{
    const float* x    = (const float*)d_in[0];
    const float* w1   = (const float*)d_in[1];
    const float* b1   = (const float*)d_in[2];
    const float* w2   = (const float*)d_in[3];
    const float* b2   = (const float*)d_in[4];
    const float* wlin = (const float*)d_in[5];
    const float* blin = (const float*)d_in[6];
    float* out = (float*)d_out;

    const size_t smem1 = 40824u * 4 + 1715u * 8;   // 177016 B
    const size_t smem2 = 20736u * 4 + 1715u * 8;   //  96664 B
    cudaFuncSetAttribute(conv1_kernel, cudaFuncAttributeMaxDynamicSharedMemorySize, (int)smem1);
    cudaFuncSetAttribute(conv2_kernel, cudaFuncAttributeMaxDynamicSharedMemorySize, (int)smem2);

    conv1_kernel<<<NB * 12, 288, smem1>>>(x, w1, b1);
    conv2_kernel<<<NB, 432, smem2>>>(w2, b2);
    linear_kernel<<<NB, 256>>>(wlin, blin, out);
}